// round 10
// baseline (speedup 1.0000x reference)
#include <cuda_runtime.h>
#include <cuda_fp16.h>
#include <math.h>

#define N_NODES 100000
#define NUM_GRAPHS 128
#define H1 4
#define C1 48
#define F1 192   // H1*C1
#define C2 96
#define D_IN 128
#define NEG_SLOPE 0.2f
#define E_MAX 1750000   // raw edges (1.6M) + self loops (100k) with slack

// ---------------- scratch (device globals; no allocation) ----------------
__device__ float g_h1[N_NODES * F1];        // x @ W1 (fp32, for attn1)
__device__ __half g_h1h[N_NODES * F1];      // fp16 copy (gather table for gat1)
__device__ float g_h1r[N_NODES * F1];       // layer1 output (relu'd)
__device__ float g_asrc1[N_NODES * H1];
__device__ float g_adst1[N_NODES * H1];
__device__ float g_h2[N_NODES * C2];        // h1r @ W2 (fp32, for attn2)
__device__ __half g_h2h[N_NODES * C2];      // fp16 copy (gather table for gat2)
__device__ float g_asrc2[N_NODES];
__device__ float g_adst2[N_NODES];
__device__ float g_pool[NUM_GRAPHS * C2];
__device__ float g_cnt[NUM_GRAPHS];
__device__ int g_src[E_MAX];
__device__ int g_dst[E_MAX];
__device__ int g_batch[N_NODES];
__device__ int g_is64;
__device__ int g_deg[N_NODES];
__device__ int g_off[N_NODES + 1];
__device__ int g_cur[N_NODES];
__device__ int g_csr_src[E_MAX];

__device__ __forceinline__ float leaky(float s) {
    return s > 0.0f ? s : NEG_SLOPE * s;
}

// ---------------- init (zero counters only) ----------------
__global__ void init_kernel() {
    int i = blockIdx.x * blockDim.x + threadIdx.x;
    int stride = gridDim.x * blockDim.x;
    for (int k = i; k < N_NODES; k += stride) g_deg[k] = 0;
    for (int k = i; k < NUM_GRAPHS * C2; k += stride) g_pool[k] = 0.0f;
    for (int k = i; k < NUM_GRAPHS; k += stride) g_cnt[k] = 0.0f;
}

// ---------------- dtype sniff: int64 vs int32 index buffers ----------------
__global__ void sniff_kernel(const unsigned int* __restrict__ w) {
    __shared__ int any_nonzero;
    if (threadIdx.x == 0) any_nonzero = 0;
    __syncthreads();
    for (int i = threadIdx.x; i < 256; i += blockDim.x) {
        if (w[2 * i + 1] != 0u) any_nonzero = 1;
    }
    __syncthreads();
    if (threadIdx.x == 0) g_is64 = (any_nonzero == 0) ? 1 : 0;
}

__global__ void decode_edges(const void* __restrict__ ei_raw, int E0) {
    int e = blockIdx.x * blockDim.x + threadIdx.x;
    int Etot = E0 + N_NODES;
    if (e >= Etot) return;
    int src, dst;
    if (e < E0) {
        if (g_is64) {
            const long long* p = (const long long*)ei_raw;
            src = (int)p[e];
            dst = (int)p[E0 + e];
        } else {
            const int* p = (const int*)ei_raw;
            src = p[e];
            dst = p[E0 + e];
        }
    } else {
        src = dst = e - E0;
    }
    g_src[e] = src;
    g_dst[e] = dst;
    atomicAdd(&g_deg[dst], 1);
}

__global__ void decode_batch(const void* __restrict__ b_raw) {
    __shared__ int hist[NUM_GRAPHS];
    for (int i = threadIdx.x; i < NUM_GRAPHS; i += blockDim.x) hist[i] = 0;
    __syncthreads();
    int n = blockIdx.x * blockDim.x + threadIdx.x;
    if (n < N_NODES) {
        int b = g_is64 ? (int)((const long long*)b_raw)[n] : ((const int*)b_raw)[n];
        g_batch[n] = b;
        atomicAdd(&hist[b], 1);
    }
    __syncthreads();
    for (int i = threadIdx.x; i < NUM_GRAPHS; i += blockDim.x)
        if (hist[i]) atomicAdd(&g_cnt[i], (float)hist[i]);
}

__global__ void scan_kernel() {
    __shared__ int part[1024];
    int t = threadIdx.x;
    const int CH = (N_NODES + 1023) / 1024;
    int lo = t * CH, hi = min(lo + CH, N_NODES);
    int s = 0;
    for (int i = lo; i < hi; i++) s += g_deg[i];
    part[t] = s;
    __syncthreads();
    for (int o = 1; o < 1024; o <<= 1) {
        int v = (t >= o) ? part[t - o] : 0;
        __syncthreads();
        part[t] += v;
        __syncthreads();
    }
    int base = (t > 0) ? part[t - 1] : 0;
    for (int i = lo; i < hi; i++) {
        g_off[i] = base;
        g_cur[i] = base;
        base += g_deg[i];
    }
    if (t == 1023) g_off[N_NODES] = part[1023];
}

__global__ void scatter_kernel(int Etot) {
    int e = blockIdx.x * blockDim.x + threadIdx.x;
    if (e >= Etot) return;
    int pos = atomicAdd(&g_cur[g_dst[e]], 1);
    g_csr_src[pos] = g_src[e];
}

// ---------------- R4-proven SGEMM + optional fp16 shadow copy ---------------
template <int TBM, int TBN, bool WRITE_HALF>
__global__ void __launch_bounds__(256) sgemm_kernel(const float* __restrict__ A,
                                                    const float* __restrict__ B,
                                                    float* __restrict__ C,
                                                    __half* __restrict__ Ch,
                                                    int M, int N, int K) {
    const int TBK = 32;
    __shared__ float As[TBK][TBM + 4];
    __shared__ float Bs[TBK][TBN + 4];

    int tid = threadIdx.x;
    int row0 = blockIdx.y * TBM;
    int col0 = blockIdx.x * TBN;
    int tx = tid % (TBN / 4);
    int ty = tid / (TBN / 4);

    float acc[8][4];
#pragma unroll
    for (int i = 0; i < 8; i++)
#pragma unroll
        for (int j = 0; j < 4; j++) acc[i][j] = 0.0f;

    const int A_F4 = TBM * TBK / 4;
    const int B_F4 = TBK * TBN / 4;

    for (int k0 = 0; k0 < K; k0 += TBK) {
#pragma unroll
        for (int it = 0; it < A_F4 / 256; it++) {
            int idA = tid + it * 256;
            int kc = idA % (TBK / 4);
            int r = idA / (TBK / 4);
            int gr = row0 + r;
            float4 v = (gr < M) ? *(const float4*)&A[(size_t)gr * K + k0 + kc * 4]
                                : make_float4(0.f, 0.f, 0.f, 0.f);
            As[kc * 4 + 0][r] = v.x;
            As[kc * 4 + 1][r] = v.y;
            As[kc * 4 + 2][r] = v.z;
            As[kc * 4 + 3][r] = v.w;
        }
#pragma unroll
        for (int it = 0; it < B_F4 / 256; it++) {
            int idB = tid + it * 256;
            int c4 = idB % (TBN / 4);
            int r = idB / (TBN / 4);
            *(float4*)&Bs[r][c4 * 4] = *(const float4*)&B[(size_t)(k0 + r) * N + col0 + c4 * 4];
        }
        __syncthreads();

#pragma unroll
        for (int k = 0; k < TBK; k++) {
            float4 a0 = *(const float4*)&As[k][ty * 8];
            float4 a1 = *(const float4*)&As[k][ty * 8 + 4];
            float4 b = *(const float4*)&Bs[k][tx * 4];
            float av[8] = {a0.x, a0.y, a0.z, a0.w, a1.x, a1.y, a1.z, a1.w};
            float bv[4] = {b.x, b.y, b.z, b.w};
#pragma unroll
            for (int i = 0; i < 8; i++)
#pragma unroll
                for (int j = 0; j < 4; j++) acc[i][j] += av[i] * bv[j];
        }
        __syncthreads();
    }

#pragma unroll
    for (int i = 0; i < 8; i++) {
        int gr = row0 + ty * 8 + i;
        if (gr < M) {
            float4 v = make_float4(acc[i][0], acc[i][1], acc[i][2], acc[i][3]);
            *(float4*)&C[(size_t)gr * N + col0 + tx * 4] = v;
            if (WRITE_HALF) {
                __half2 h01 = __floats2half2_rn(v.x, v.y);
                __half2 h23 = __floats2half2_rn(v.z, v.w);
                *(__half2*)&Ch[(size_t)gr * N + col0 + tx * 4] = h01;
                *(__half2*)&Ch[(size_t)gr * N + col0 + tx * 4 + 2] = h23;
            }
        }
    }
}

// ---------------- attention scalars ----------------
__global__ void attn1_kernel(const float* __restrict__ a_src, const float* __restrict__ a_dst) {
    int idx = blockIdx.x * blockDim.x + threadIdx.x;
    if (idx >= N_NODES * H1) return;
    int n = idx >> 2, h = idx & 3;
    const float* hp = &g_h1[(size_t)n * F1 + h * C1];
    const float* ws = &a_src[h * C1];
    const float* wd = &a_dst[h * C1];
    float ss = 0.0f, sd = 0.0f;
#pragma unroll
    for (int j = 0; j < C1; j++) {
        float v = hp[j];
        ss += v * ws[j];
        sd += v * wd[j];
    }
    g_asrc1[idx] = ss;
    g_adst1[idx] = sd;
}

__global__ void attn2_kernel(const float* __restrict__ a_src, const float* __restrict__ a_dst) {
    int w = (blockIdx.x * blockDim.x + threadIdx.x) >> 5;
    int lane = threadIdx.x & 31;
    if (w >= N_NODES) return;
    const float* hp = &g_h2[(size_t)w * C2];
    float ss = 0.0f, sd = 0.0f;
#pragma unroll
    for (int k = 0; k < 3; k++) {
        int j = lane + 32 * k;
        float v = hp[j];
        ss += v * a_src[j];
        sd += v * a_dst[j];
    }
#pragma unroll
    for (int o = 16; o > 0; o >>= 1) {
        ss += __shfl_down_sync(0xffffffffu, ss, o);
        sd += __shfl_down_sync(0xffffffffu, sd, o);
    }
    if (lane == 0) {
        g_asrc2[w] = ss;
        g_adst2[w] = sd;
    }
}

// ---------------- layer 1 fused: register-shuffle softmax, fp16 half2 gather ----
// lane owns channel pairs (2L, 2L+1), (64+2L, 64+2L+1), (128+2L, 128+2L+1);
// head boundaries 48/96/144 are even -> each pair lies in one head.
__global__ void gat1_kernel(const float* __restrict__ b1) {
    int node = (blockIdx.x * blockDim.x + threadIdx.x) >> 5;
    int lane = threadIdx.x & 31;
    if (node >= N_NODES) return;
    int start = g_off[node], end = g_off[node + 1];

    float4 ad = *(const float4*)&g_adst1[node * H1];

    // pass A: per-lane exp scores for round 0 stay in registers; den over all edges
    int src0 = 0;
    float4 p0 = make_float4(0.f, 0.f, 0.f, 0.f);
    float4 den = make_float4(0.f, 0.f, 0.f, 0.f);
    {
        int idx = start + lane;
        if (idx < end) {
            src0 = g_csr_src[idx];
            float4 as = *(const float4*)&g_asrc1[src0 * H1];
            p0.x = __expf(leaky(as.x + ad.x));
            p0.y = __expf(leaky(as.y + ad.y));
            p0.z = __expf(leaky(as.z + ad.z));
            p0.w = __expf(leaky(as.w + ad.w));
            den = p0;
        }
        for (int base = start + 32; base < end; base += 32) {
            int i2 = base + lane;
            if (i2 < end) {
                int s = g_csr_src[i2];
                float4 as = *(const float4*)&g_asrc1[s * H1];
                den.x += __expf(leaky(as.x + ad.x));
                den.y += __expf(leaky(as.y + ad.y));
                den.z += __expf(leaky(as.z + ad.z));
                den.w += __expf(leaky(as.w + ad.w));
            }
        }
    }
#pragma unroll
    for (int o = 16; o > 0; o >>= 1) {
        den.x += __shfl_xor_sync(0xffffffffu, den.x, o);
        den.y += __shfl_xor_sync(0xffffffffu, den.y, o);
        den.z += __shfl_xor_sync(0xffffffffu, den.z, o);
        den.w += __shfl_xor_sync(0xffffffffu, den.w, o);
    }
    float inv0 = 1.0f / den.x, inv1 = 1.0f / den.y, inv2 = 1.0f / den.z, inv3 = 1.0f / den.w;

    // per-lane channel/head mapping (constants across edges)
    int cA = 2 * lane;            // 0..62    head {0,1}
    int cB = 64 + 2 * lane;       // 64..126  head {1,2}
    int cC = 128 + 2 * lane;      // 128..190 head {2,3}
    bool selA = cA < 48, selB = cB < 96, selC = cC < 144;
    float invA = selA ? inv0 : inv1;
    float invB = selB ? inv1 : inv2;
    float invC = selC ? inv2 : inv3;

    float2 acc0 = make_float2(0.f, 0.f);
    float2 acc1 = make_float2(0.f, 0.f);
    float2 acc2 = make_float2(0.f, 0.f);

    for (int base = start; base < end; base += 32) {
        int cnt = min(32, end - base);
        int sL;
        float4 pL;
        if (base == start) {
            sL = src0;
            pL = p0;
        } else {  // rare (deg > 32): recompute scores for this round
            int idx = base + lane;
            sL = 0;
            pL = make_float4(0.f, 0.f, 0.f, 0.f);
            if (idx < end) {
                sL = g_csr_src[idx];
                float4 as = *(const float4*)&g_asrc1[sL * H1];
                pL.x = __expf(leaky(as.x + ad.x));
                pL.y = __expf(leaky(as.y + ad.y));
                pL.z = __expf(leaky(as.z + ad.z));
                pL.w = __expf(leaky(as.w + ad.w));
            }
        }
#pragma unroll 4
        for (int j = 0; j < cnt; j++) {
            int src = __shfl_sync(0xffffffffu, sL, j);
            float px = __shfl_sync(0xffffffffu, pL.x, j);
            float py = __shfl_sync(0xffffffffu, pL.y, j);
            float pz = __shfl_sync(0xffffffffu, pL.z, j);
            float pw = __shfl_sync(0xffffffffu, pL.w, j);
            float aA = (selA ? px : py) * invA;
            float aB = (selB ? py : pz) * invB;
            float aC = (selC ? pz : pw) * invC;
            const __half* hp = &g_h1h[(size_t)src * F1];
            float2 f0 = __half22float2(*(const __half2*)&hp[cA]);
            float2 f1 = __half22float2(*(const __half2*)&hp[cB]);
            float2 f2 = __half22float2(*(const __half2*)&hp[cC]);
            acc0.x += f0.x * aA; acc0.y += f0.y * aA;
            acc1.x += f1.x * aB; acc1.y += f1.y * aB;
            acc2.x += f2.x * aC; acc2.y += f2.y * aC;
        }
    }

    float2 bA = *(const float2*)&b1[cA];
    float2 bB = *(const float2*)&b1[cB];
    float2 bC = *(const float2*)&b1[cC];
    float* op = &g_h1r[(size_t)node * F1];
    *(float2*)&op[cA] = make_float2(fmaxf(acc0.x + bA.x, 0.f), fmaxf(acc0.y + bA.y, 0.f));
    *(float2*)&op[cB] = make_float2(fmaxf(acc1.x + bB.x, 0.f), fmaxf(acc1.y + bB.y, 0.f));
    *(float2*)&op[cC] = make_float2(fmaxf(acc2.x + bC.x, 0.f), fmaxf(acc2.y + bC.y, 0.f));
}

// ---------------- layer 2 fused: register-shuffle softmax + pool ------------
// lane owns channel pair (2L, 2L+1) and scalar 64+L.
__global__ void gat2_kernel(const float* __restrict__ b2) {
    int node = (blockIdx.x * blockDim.x + threadIdx.x) >> 5;
    int lane = threadIdx.x & 31;
    if (node >= N_NODES) return;
    int start = g_off[node], end = g_off[node + 1];

    float ad = g_adst2[node];
    int src0 = 0;
    float p0 = 0.0f;
    float den = 0.0f;
    {
        int idx = start + lane;
        if (idx < end) {
            src0 = g_csr_src[idx];
            p0 = __expf(leaky(g_asrc2[src0] + ad));
            den = p0;
        }
        for (int base = start + 32; base < end; base += 32) {
            int i2 = base + lane;
            if (i2 < end) {
                int s = g_csr_src[i2];
                den += __expf(leaky(g_asrc2[s] + ad));
            }
        }
    }
#pragma unroll
    for (int o = 16; o > 0; o >>= 1) den += __shfl_xor_sync(0xffffffffu, den, o);
    float inv = 1.0f / den;

    int cA = 2 * lane;     // pairs 0..63
    int cB = 64 + lane;    // scalars 64..95
    float2 accA = make_float2(0.f, 0.f);
    float accB = 0.0f;

    for (int base = start; base < end; base += 32) {
        int cnt = min(32, end - base);
        int sL;
        float pL;
        if (base == start) {
            sL = src0;
            pL = p0;
        } else {
            int idx = base + lane;
            sL = 0;
            pL = 0.0f;
            if (idx < end) {
                sL = g_csr_src[idx];
                pL = __expf(leaky(g_asrc2[sL] + ad));
            }
        }
#pragma unroll 4
        for (int j = 0; j < cnt; j++) {
            int src = __shfl_sync(0xffffffffu, sL, j);
            float alpha = __shfl_sync(0xffffffffu, pL, j) * inv;
            const __half* hp = &g_h2h[(size_t)src * C2];
            float2 fA = __half22float2(*(const __half2*)&hp[cA]);
            float fB = __half2float(hp[cB]);
            accA.x += fA.x * alpha;
            accA.y += fA.y * alpha;
            accB += fB * alpha;
        }
    }

    int gp = g_batch[node] * C2;
    atomicAdd(&g_pool[gp + cA], fmaxf(accA.x + b2[cA], 0.0f));
    atomicAdd(&g_pool[gp + cA + 1], fmaxf(accA.y + b2[cA + 1], 0.0f));
    atomicAdd(&g_pool[gp + cB], fmaxf(accB + b2[cB], 0.0f));
}

// ---------------- final MLP: one block per graph ----------------
__global__ void mlp_kernel(const float* __restrict__ fc1_w, const float* __restrict__ fc1_b,
                           const float* __restrict__ fc2_w, const float* __restrict__ fc2_b,
                           float* __restrict__ out) {
    __shared__ float p[C2];
    __shared__ float z[192];
    int g = blockIdx.x;
    int t = threadIdx.x;
    float inv = 1.0f / fmaxf(g_cnt[g], 1.0f);
    if (t < C2) p[t] = g_pool[g * C2 + t] * inv;
    __syncthreads();
    float acc = fc1_b[t];
#pragma unroll
    for (int k = 0; k < C2; k++) acc += p[k] * fc1_w[k * 192 + t];
    z[t] = fmaxf(acc, 0.0f);
    __syncthreads();
    if (t < C2) {
        float o = fc2_b[t];
#pragma unroll
        for (int k = 0; k < 192; k++) o += z[k] * fc2_w[k * C2 + t];
        out[g * C2 + t] = o;
    }
}

// ---------------- host launch (two-stream overlap, capture-legal) ----------
extern "C" void kernel_launch(void* const* d_in, const int* in_sizes, int n_in,
                              void* d_out, int out_size) {
    const float* x = (const float*)d_in[0];
    const void* ei_raw = d_in[1];
    const void* batch_raw = d_in[2];
    const float* W1 = (const float*)d_in[3];
    const float* a_src1 = (const float*)d_in[4];
    const float* a_dst1 = (const float*)d_in[5];
    const float* b1 = (const float*)d_in[6];
    const float* W2 = (const float*)d_in[7];
    const float* a_src2 = (const float*)d_in[8];
    const float* a_dst2 = (const float*)d_in[9];
    const float* b2 = (const float*)d_in[10];
    const float* fc1_w = (const float*)d_in[11];
    const float* fc1_b = (const float*)d_in[12];
    const float* fc2_w = (const float*)d_in[13];
    const float* fc2_b = (const float*)d_in[14];
    float* out = (float*)d_out;

    int E0 = in_sizes[1] / 2;
    int Etot = E0 + N_NODES;

    float *h1p, *h1rp, *h2p;
    __half *h1hp, *h2hp;
    cudaGetSymbolAddress((void**)&h1p, g_h1);
    cudaGetSymbolAddress((void**)&h1rp, g_h1r);
    cudaGetSymbolAddress((void**)&h2p, g_h2);
    cudaGetSymbolAddress((void**)&h1hp, g_h1h);
    cudaGetSymbolAddress((void**)&h2hp, g_h2h);

    // fork a side stream for graph preprocessing
    cudaStream_t sB;
    cudaStreamCreateWithFlags(&sB, cudaStreamNonBlocking);
    cudaEvent_t evFork, evJoin;
    cudaEventCreateWithFlags(&evFork, cudaEventDisableTiming);
    cudaEventCreateWithFlags(&evJoin, cudaEventDisableTiming);

    cudaEventRecord(evFork, 0);
    cudaStreamWaitEvent(sB, evFork, 0);

    // ---- stream B: CSR build + batch decode ----
    init_kernel<<<256, 256, 0, sB>>>();
    sniff_kernel<<<1, 256, 0, sB>>>((const unsigned int*)ei_raw);
    decode_edges<<<(Etot + 255) / 256, 256, 0, sB>>>(ei_raw, E0);
    decode_batch<<<(N_NODES + 255) / 256, 256, 0, sB>>>(batch_raw);
    scan_kernel<<<1, 1024, 0, sB>>>();
    scatter_kernel<<<(Etot + 255) / 256, 256, 0, sB>>>(Etot);
    cudaEventRecord(evJoin, sB);

    // ---- default stream: GEMM1 (+fp16 shadow) + attn1 ----
    {
        dim3 grid(F1 / 64, (N_NODES + 127) / 128);
        sgemm_kernel<128, 64, true><<<grid, 256>>>(x, W1, h1p, h1hp, N_NODES, F1, D_IN);
    }
    attn1_kernel<<<(N_NODES * H1 + 255) / 256, 256>>>(a_src1, a_dst1);

    // join: gat1 needs both chains
    cudaStreamWaitEvent(0, evJoin, 0);

    gat1_kernel<<<(N_NODES + 7) / 8, 256>>>(b1);

    // layer 2
    {
        dim3 grid(C2 / 32, (N_NODES + 255) / 256);
        sgemm_kernel<256, 32, true><<<grid, 256>>>(h1rp, W2, h2p, h2hp, N_NODES, C2, F1);
    }
    attn2_kernel<<<(N_NODES * 32 + 255) / 256, 256>>>(a_src2, a_dst2);
    gat2_kernel<<<(N_NODES + 7) / 8, 256>>>(b2);

    // MLP head
    mlp_kernel<<<NUM_GRAPHS, 192>>>(fc1_w, fc1_b, fc2_w, fc2_b, out);
}